// round 14
// baseline (speedup 1.0000x reference)
#include <cuda_runtime.h>
#include <cstdint>

#define KTOT   4194304
#define CHUNK  64                      // outputs per chain
#define WARM   128                     // warmup window (tile alignment)
#define TS     32                      // steps per tile
#define NT     6                       // tiles per chain
#define WTILES 4                       // warmup tiles (tile 0 half-skipped: eff 112)
#define NCH    (KTOT / CHUNK)          // 65536 chains (1 per thread)
#define WPB    2                       // warps per block
#define TPB    (WPB * 32)
#define NBLK   (NCH / 32 / WPB)        // 1024 blocks (2048 warps)
#define PITCH  34                      // buffer row pitch in floats
#define BROWS  34                      // rows per parity buffer (32 + 2 shift)
#define SGP    18                      // sigma half-buffer pitch

__device__ __forceinline__ float frcp_ap(float x) {
    float r; asm("rcp.approx.ftz.f32 %0, %1;" : "=f"(r) : "f"(x)); return r;
}
__device__ __forceinline__ float fsqrt_ap(float x) {
    float r; asm("sqrt.approx.f32 %0, %1;" : "=f"(r) : "f"(x)); return r;
}
__device__ __forceinline__ void cp_async8(uint32_t dst, const float* src) {
    asm volatile("cp.async.ca.shared.global [%0], [%1], 8;" :: "r"(dst), "l"(src));
}
#define CP_COMMIT() asm volatile("cp.async.commit_group;" ::: "memory")
#define CP_WAIT1()  asm volatile("cp.async.wait_group 1;"  ::: "memory")
#define CP_WAIT0()  asm volatile("cp.async.wait_group 0;"  ::: "memory")

struct P { float nu, Amu, As, bmu, Bs, wmu, ws; };

__device__ __forceinline__ void gas_step(const float y, float& mu, float& s2, const P& p) {
    // scale*r = (nu+1)*s2*r/(nu*s2+r^2). Dual-product: mu',s2' one fma after q.
    const float r_   = y - mu;
    const float rr   = r_ * r_;
    const float d    = fmaf(p.nu, s2, rr);
    const float q    = frcp_ap(d);
    const float s2r  = s2 * r_;                  // parallel with d/q
    const float s2rr = s2 * rr;                  // parallel with d/q
    const float mb   = fmaf(p.bmu, mu, p.wmu);   // off critical path
    const float sb   = fmaf(p.Bs,  s2, p.ws);    // off critical path
    mu = fmaf(p.Amu, s2r  * q, mb);
    s2 = fmaf(p.As,  s2rr * q, sb);
}

// Stage ALL 34 rows of a parity buffer (17 cp.async8 per lane, one group).
template<bool GUARD>
__device__ __forceinline__ void stage_full(
    const int base, const int lane, const float* __restrict__ y, float* buf)
{
    const int r0  = lane >> 4;
    const int col = (lane & 15) * 2;
    uint32_t dst = (uint32_t)__cvta_generic_to_shared(buf + r0 * PITCH + col);
    const int g0 = base + r0 * 64 + col;
    #pragma unroll
    for (int k = 0; k < 17; ++k) {               // rows 2k+r0 = 0..33
        int g = g0 + k * 128;
        if (GUARD) g = max(g, 0);                // warp0 pre-t0 slots: skipped
        cp_async8(dst + (uint32_t)(k * (2 * PITCH * 4)), y + g);
    }
    CP_COMMIT();
}

// 16 steps (half tile) from a register preload out of smem. EMIT: mu in place.
template<bool GUARD, bool EMIT>
__device__ __forceinline__ void do_half(
    const int t, const int h, const int skip,
    float* rp, float* sgr, float& mu, float& s2, const P& p)
{
    float2 v[8];
    #pragma unroll
    for (int i = 0; i < 8; ++i)                  // 8-deep LDS.64 burst (MLP)
        v[i] = *reinterpret_cast<const float2*>(rp + 16 * h + 2 * i);
    #pragma unroll
    for (int i = 0; i < 8; ++i) {
        if (GUARD) {
            if (t * TS + 16 * h + 2 * i     >= skip) gas_step(v[i].x, mu, s2, p);
            if (t * TS + 16 * h + 2 * i + 1 >= skip) gas_step(v[i].y, mu, s2, p);
        } else {
            gas_step(v[i].x, mu, s2, p);
            const float m0 = mu, v0 = s2;
            gas_step(v[i].y, mu, s2, p);
            if (EMIT) {
                *reinterpret_cast<float2*>(rp + 16 * h + 2 * i) = make_float2(m0, mu);
                *reinterpret_cast<float2*>(sgr + 2 * i)         = make_float2(v0, s2);
            }
        }
    }
}

// 2*n steps straight from an LDG-register preload (no smem dependence).
template<bool GUARD, int N2>
__device__ __forceinline__ void do_regs(
    const int step0, const int skip, const float2* v,
    float& mu, float& s2, const P& p)
{
    #pragma unroll
    for (int i = 0; i < N2; ++i) {
        if (GUARD) {
            if (step0 + 2 * i     >= skip) gas_step(v[i].x, mu, s2, p);
            if (step0 + 2 * i + 1 >= skip) gas_step(v[i].y, mu, s2, p);
        } else {
            gas_step(v[i].x, mu, s2, p);
            gas_step(v[i].y, mu, s2, p);
        }
    }
}

__device__ __forceinline__ void flush_sigma_half(
    const int t, const int h, const int wcb, const int lane,
    const float* sg, float* __restrict__ out)
{
    const int r0 = lane >> 3;
    const int c  = (lane & 7) * 2;
    const int ob = (t - WTILES) * TS + 16 * h;
    #pragma unroll
    for (int k = 0; k < 8; ++k) {
        const int row = 4 * k + r0;
        float2 g = *reinterpret_cast<const float2*>(sg + row * SGP + c);
        g.x = fsqrt_ap(g.x); g.y = fsqrt_ap(g.y);
        *reinterpret_cast<float2*>(&out[KTOT + (wcb + row) * CHUNK + ob + c]) = g;
    }
}

__device__ __forceinline__ void flush_mu(
    const int t, const int ro, const int wcb, const int lane,
    const float* bp, float* __restrict__ out)
{
    const int r0  = lane >> 4;
    const int col = (lane & 15) * 2;
    const int ob  = (t - WTILES) * TS;
    #pragma unroll
    for (int k = 0; k < 16; ++k) {
        const int row = 2 * k + r0;
        const float2 m = *reinterpret_cast<const float2*>(
            bp + (row + ro) * PITCH + col);
        *reinterpret_cast<float2*>(&out[(wcb + row) * CHUNK + ob + col]) = m;
    }
}

template<bool GUARD>
__device__ __forceinline__ void run_warp(
    const int wcb, const int lane,
    const float* __restrict__ y, float* __restrict__ out,
    float* bufE, float* bufO, float* sg,
    float mu, float s2, const P& p, const int skip)
{
    const int baseE = wcb * CHUNK - WARM;        // row r of E = y[baseE+64r,+32)
    const int baseO = baseE + 32;                // row r of O = y[baseO+64r,+32)

    // ---- register prefetch of tiles 0 (2nd half) and 1: own 384B via LDG ----
    float2 va[8], vb[16];
    {
        const int a0 = baseE + 64 * lane + 16;   // tile0 steps 16..31
        const int b0 = baseO + 64 * lane;        // tile1 steps 0..31
        #pragma unroll
        for (int i = 0; i < 8; ++i) {
            int g = a0 + 2 * i;
            if (GUARD) g = max(g, 0);
            va[i] = *reinterpret_cast<const float2*>(y + g);
        }
        #pragma unroll
        for (int i = 0; i < 16; ++i) {
            int g = b0 + 2 * i;
            if (GUARD) g = max(g, 0);
            vb[i] = *reinterpret_cast<const float2*>(y + g);
        }
    }

    // ---- stream the full parity buffers behind the register compute ----
    stage_full<GUARD>(baseE, lane, y, bufE);     // group 0
    stage_full<GUARD>(baseO, lane, y, bufO);     // group 1

    // tiles 0 (half) and 1 from registers — no cp.async dependence
    do_regs<GUARD, 8 >(16, skip, va, mu, s2, p);
    do_regs<GUARD, 16>(32, skip, vb, mu, s2, p);

    float* sgr = sg + lane * SGP;

    // tiles 2..5 from smem (rows lane+1 for t=2,3; lane+2 for t=4,5)
    #pragma unroll 1
    for (int t = 2; t < NT; ++t) {
        if (t == 2) CP_WAIT1();                  // E resident
        else if (t == 3) CP_WAIT0();             // O resident
        __syncwarp();
        float* bp = (t & 1) ? bufO : bufE;
        const int ro = t >> 1;
        float* rp = bp + (lane + ro) * PITCH;

        if (t < WTILES) {
            if (GUARD) {
                do_half<true,  false>(t, 0, skip, rp, sgr, mu, s2, p);
                do_half<true,  false>(t, 1, skip, rp, sgr, mu, s2, p);
            } else {
                do_half<false, false>(t, 0, skip, rp, sgr, mu, s2, p);
                do_half<false, false>(t, 1, skip, rp, sgr, mu, s2, p);
            }
        } else {
            #pragma unroll
            for (int h = 0; h < 2; ++h) {
                do_half<false, true>(t, h, skip, rp, sgr, mu, s2, p);
                __syncwarp();
                flush_sigma_half(t, h, wcb, lane, sg, out);
                __syncwarp();                    // sg reads done before reuse
            }
            flush_mu(t, ro, wcb, lane, bp, out);
        }
    }
}

__global__ __launch_bounds__(TPB)
void argas_kernel(
    const float* __restrict__ y,
    const float* __restrict__ p_lastmu,  const float* __restrict__ p_lastsig,
    const float* __restrict__ p_amu,     const float* __restrict__ p_as,
    const float* __restrict__ p_bmu,     const float* __restrict__ p_bs,
    const float* __restrict__ p_wmu,     const float* __restrict__ p_ws,
    const float* __restrict__ p_nu,      const float* __restrict__ p_str,
    float* __restrict__ out)
{
    __shared__ float bufE[WPB][BROWS][PITCH];   // per-warp even-parity rows
    __shared__ float bufO[WPB][BROWS][PITCH];   // per-warp odd-parity rows
    __shared__ float sg[WPB][32][SGP];          // per-warp sigma half-buffer

    const int warp  = threadIdx.x >> 5;
    const int lane  = threadIdx.x & 31;
    const int wcb   = (blockIdx.x * WPB + warp) * 32;   // warp's chain base
    const int chain = wcb + lane;

    P p;
    const float nu       = *p_nu;
    const float strength = *p_str;
    const float amu  = (*p_amu) * strength;
    const float as_  = (*p_as)  * strength;
    const float bmu  = *p_bmu;
    const float bs   = *p_bs;
    const float nup1 = nu + 1.0f;
    p.nu  = nu;
    p.Amu = bmu * amu * nup1;
    p.As  = bs  * as_ * nup1;
    p.bmu = bmu;
    p.Bs  = bs * (1.0f - as_);
    p.wmu = *p_wmu;
    p.ws  = *p_ws;

    const float mu0 = *p_lastmu;   // chains whose warmup reaches before idx 0
    const float s20 = *p_lastsig;  // skip those steps; they start exact.

    const int skip = WARM - chain * CHUNK;   // >0 only for chains 0,1 (warp 0)

    if (wcb == 0)
        run_warp<true >(wcb, lane, y, out,
                        &bufE[warp][0][0], &bufO[warp][0][0], &sg[warp][0][0],
                        mu0, s20, p, skip);
    else
        run_warp<false>(wcb, lane, y, out,
                        &bufE[warp][0][0], &bufO[warp][0][0], &sg[warp][0][0],
                        mu0, s20, p, skip);
}

extern "C" void kernel_launch(void* const* d_in, const int* in_sizes, int n_in,
                              void* d_out, int out_size) {
    const float* y = (const float*)d_in[0];
    argas_kernel<<<NBLK, TPB>>>(
        y,
        (const float*)d_in[1],  (const float*)d_in[2],
        (const float*)d_in[3],  (const float*)d_in[4],
        (const float*)d_in[5],  (const float*)d_in[6],
        (const float*)d_in[7],  (const float*)d_in[8],
        (const float*)d_in[9],  (const float*)d_in[10],
        (float*)d_out);
}

// round 15
// speedup vs baseline: 1.3012x; 1.3012x over previous
#include <cuda_runtime.h>
#include <cstdint>

#define KTOT   4194304
#define CHUNK  64                      // outputs per chain
#define WARM   128                     // warmup window (tile alignment)
#define TS     32                      // steps per tile
#define NT     6                       // tiles per chain
#define WTILES 4                       // warmup tiles (tile 0 half-skipped: eff 112)
#define NCH    (KTOT / CHUNK)          // 65536 chains (1 per thread)
#define WPB    2                       // warps per block
#define TPB    (WPB * 32)
#define NBLK   (NCH / 32 / WPB)        // 1024 blocks (2048 warps)
#define PITCH  34                      // buffer row pitch in floats
#define BROWS  34                      // rows per parity buffer (32 + 2 shift)
#define SGP    18                      // sigma half-buffer pitch

__device__ __forceinline__ float fsqrt_ap(float x) {
    float r; asm("sqrt.approx.f32 %0, %1;" : "=f"(r) : "f"(x)); return r;
}
// Pure-FMA reciprocal: bit-trick seed + 3 Newton iterations (rel err ~1e-10).
// Keeps the per-step critical chain entirely on the fma pipe (no MUFU).
__device__ __forceinline__ float nrcp(float x) {
    float q = __int_as_float(0x7EF311C3 - __float_as_int(x));
    q = q * fmaf(-x, q, 2.0f);
    q = q * fmaf(-x, q, 2.0f);
    q = q * fmaf(-x, q, 2.0f);
    return q;
}
__device__ __forceinline__ void cp_async8(uint32_t dst, const float* src) {
    asm volatile("cp.async.ca.shared.global [%0], [%1], 8;" :: "r"(dst), "l"(src));
}
#define CP_COMMIT() asm volatile("cp.async.commit_group;" ::: "memory")
#define CP_WAIT1()  asm volatile("cp.async.wait_group 1;"  ::: "memory")
#define CP_WAIT0()  asm volatile("cp.async.wait_group 0;"  ::: "memory")

struct P { float nu, Amu, As, bmu, Bs, wmu, ws; };

__device__ __forceinline__ void gas_step(const float y, float& mu, float& s2, const P& p) {
    // scale*r = (nu+1)*s2*r/(nu*s2+r^2). Dual-product: mu',s2' one fma after q.
    const float r_   = y - mu;
    const float rr   = r_ * r_;
    const float d    = fmaf(p.nu, s2, rr);
    const float q    = nrcp(d);                  // pure-FMA reciprocal
    const float s2r  = s2 * r_;                  // parallel with d/q
    const float s2rr = s2 * rr;                  // parallel with d/q
    const float mb   = fmaf(p.bmu, mu, p.wmu);   // off critical path
    const float sb   = fmaf(p.Bs,  s2, p.ws);    // off critical path
    mu = fmaf(p.Amu, s2r  * q, mb);
    s2 = fmaf(p.As,  s2rr * q, sb);
}

// Stage rows 0..31 of a parity buffer. Row r holds y[base + 64r, +32).
template<bool GUARD>
__device__ __forceinline__ void stage_init(
    const int base, const int lane, const float* __restrict__ y, float* buf)
{
    const int r0  = lane >> 4;
    const int col = (lane & 15) * 2;
    uint32_t dst = (uint32_t)__cvta_generic_to_shared(buf + r0 * PITCH + col);
    const int g0 = base + r0 * 64 + col;
    #pragma unroll
    for (int k = 0; k < 16; ++k) {               // rows 2k+r0 = 0..31
        int g = g0 + k * 128;
        if (GUARD) g = max(g, 0);                // warp0 pre-t0 slots: skipped
        cp_async8(dst + (uint32_t)(k * (2 * PITCH * 4)), y + g);
    }
    CP_COMMIT();
}

// Stage one extension row (32 floats) of a parity buffer; all lanes commit.
__device__ __forceinline__ void stage_row(
    const int row, const int base, const int lane,
    const float* __restrict__ y, float* buf)
{
    if (lane < 16) {
        uint32_t dst = (uint32_t)__cvta_generic_to_shared(buf + row * PITCH + lane * 2);
        cp_async8(dst, y + base + 64 * row + lane * 2);   // always >= 0 here
    }
    CP_COMMIT();
}

// 16 steps (half tile) from a register preload. EMIT: mu in place, s2 -> sgr.
template<bool GUARD, bool EMIT>
__device__ __forceinline__ void do_half(
    const int t, const int h, const int skip,
    float* rp, float* sgr, float& mu, float& s2, const P& p)
{
    float2 v[8];
    #pragma unroll
    for (int i = 0; i < 8; ++i)                  // 8-deep LDS.64 burst (MLP)
        v[i] = *reinterpret_cast<const float2*>(rp + 16 * h + 2 * i);
    #pragma unroll
    for (int i = 0; i < 8; ++i) {
        if (GUARD) {
            if (t * TS + 16 * h + 2 * i     >= skip) gas_step(v[i].x, mu, s2, p);
            if (t * TS + 16 * h + 2 * i + 1 >= skip) gas_step(v[i].y, mu, s2, p);
        } else {
            gas_step(v[i].x, mu, s2, p);
            const float m0 = mu, v0 = s2;
            gas_step(v[i].y, mu, s2, p);
            if (EMIT) {
                *reinterpret_cast<float2*>(rp + 16 * h + 2 * i) = make_float2(m0, mu);
                *reinterpret_cast<float2*>(sgr + 2 * i)         = make_float2(v0, s2);
            }
        }
    }
}

// Flush one sigma half: 32 chains x 16 steps, sqrt applied here.
__device__ __forceinline__ void flush_sigma_half(
    const int t, const int h, const int wcb, const int lane,
    const float* sg, float* __restrict__ out)
{
    const int r0 = lane >> 3;
    const int c  = (lane & 7) * 2;
    const int ob = (t - WTILES) * TS + 16 * h;
    #pragma unroll
    for (int k = 0; k < 8; ++k) {
        const int row = 4 * k + r0;
        float2 g = *reinterpret_cast<const float2*>(sg + row * SGP + c);
        g.x = fsqrt_ap(g.x); g.y = fsqrt_ap(g.y);
        *reinterpret_cast<float2*>(&out[KTOT + (wcb + row) * CHUNK + ob + c]) = g;
    }
}

// Flush mu for a whole emit tile: chain i's data sits at buffer row i+ro.
__device__ __forceinline__ void flush_mu(
    const int t, const int ro, const int wcb, const int lane,
    const float* bp, float* __restrict__ out)
{
    const int r0  = lane >> 4;
    const int col = (lane & 15) * 2;
    const int ob  = (t - WTILES) * TS;
    #pragma unroll
    for (int k = 0; k < 16; ++k) {
        const int row = 2 * k + r0;
        const float2 m = *reinterpret_cast<const float2*>(
            bp + (row + ro) * PITCH + col);
        *reinterpret_cast<float2*>(&out[(wcb + row) * CHUNK + ob + col]) = m;
    }
}

template<bool GUARD>
__device__ __forceinline__ void run_warp(
    const int wcb, const int lane,
    const float* __restrict__ y, float* __restrict__ out,
    float* bufE, float* bufO, float* sg,
    float mu, float s2, const P& p, const int skip)
{
    const int baseE = wcb * CHUNK - WARM;        // row r of E = y[baseE+64r,+32)
    const int baseO = baseE + 32;                // row r of O = y[baseO+64r,+32)

    stage_init<GUARD>(baseE, lane, y, bufE);     // group 0
    stage_init<GUARD>(baseO, lane, y, bufO);     // group 1

    float* sgr = sg + lane * SGP;

    #pragma unroll 1
    for (int t = 0; t < NT; ++t) {
        if (t < NT - 1) CP_WAIT1(); else CP_WAIT0();
        __syncwarp();
        float* bp = (t & 1) ? bufO : bufE;
        const int ro = t >> 1;
        float* rp = bp + (lane + ro) * PITCH;

        // stage extension row for tile t+2 (same parity): rows 32,32,33,33
        if (t + 2 < NT)
            stage_row(31 + ((t + 2) >> 1), (t & 1) ? baseO : baseE, lane, y, bp);

        if (t < WTILES) {
            if (GUARD) {
                if (t > 0) do_half<true, false>(t, 0, skip, rp, sgr, mu, s2, p);
                do_half<true,  false>(t, 1, skip, rp, sgr, mu, s2, p);
            } else {
                // tile 0: skip first half -> effective warmup = 112 steps
                if (t > 0) do_half<false, false>(t, 0, skip, rp, sgr, mu, s2, p);
                do_half<false, false>(t, 1, skip, rp, sgr, mu, s2, p);
            }
        } else {
            #pragma unroll
            for (int h = 0; h < 2; ++h) {
                do_half<false, true>(t, h, skip, rp, sgr, mu, s2, p);
                __syncwarp();
                flush_sigma_half(t, h, wcb, lane, sg, out);
                __syncwarp();                    // sg reads done before reuse
            }
            flush_mu(t, ro, wcb, lane, bp, out);
        }
    }
}

__global__ __launch_bounds__(TPB)
void argas_kernel(
    const float* __restrict__ y,
    const float* __restrict__ p_lastmu,  const float* __restrict__ p_lastsig,
    const float* __restrict__ p_amu,     const float* __restrict__ p_as,
    const float* __restrict__ p_bmu,     const float* __restrict__ p_bs,
    const float* __restrict__ p_wmu,     const float* __restrict__ p_ws,
    const float* __restrict__ p_nu,      const float* __restrict__ p_str,
    float* __restrict__ out)
{
    __shared__ float bufE[WPB][BROWS][PITCH];   // per-warp even-parity rows
    __shared__ float bufO[WPB][BROWS][PITCH];   // per-warp odd-parity rows
    __shared__ float sg[WPB][32][SGP];          // per-warp sigma half-buffer

    const int warp  = threadIdx.x >> 5;
    const int lane  = threadIdx.x & 31;
    const int wcb   = (blockIdx.x * WPB + warp) * 32;   // warp's chain base
    const int chain = wcb + lane;

    P p;
    const float nu       = *p_nu;
    const float strength = *p_str;
    const float amu  = (*p_amu) * strength;
    const float as_  = (*p_as)  * strength;
    const float bmu  = *p_bmu;
    const float bs   = *p_bs;
    const float nup1 = nu + 1.0f;
    p.nu  = nu;
    p.Amu = bmu * amu * nup1;
    p.As  = bs  * as_ * nup1;
    p.bmu = bmu;
    p.Bs  = bs * (1.0f - as_);
    p.wmu = *p_wmu;
    p.ws  = *p_ws;

    const float mu0 = *p_lastmu;   // chains whose warmup reaches before idx 0
    const float s20 = *p_lastsig;  // skip those steps; they start exact.

    const int skip = WARM - chain * CHUNK;   // >0 only for chains 0,1 (warp 0)

    if (wcb == 0)
        run_warp<true >(wcb, lane, y, out,
                        &bufE[warp][0][0], &bufO[warp][0][0], &sg[warp][0][0],
                        mu0, s20, p, skip);
    else
        run_warp<false>(wcb, lane, y, out,
                        &bufE[warp][0][0], &bufO[warp][0][0], &sg[warp][0][0],
                        mu0, s20, p, skip);
}

extern "C" void kernel_launch(void* const* d_in, const int* in_sizes, int n_in,
                              void* d_out, int out_size) {
    const float* y = (const float*)d_in[0];
    argas_kernel<<<NBLK, TPB>>>(
        y,
        (const float*)d_in[1],  (const float*)d_in[2],
        (const float*)d_in[3],  (const float*)d_in[4],
        (const float*)d_in[5],  (const float*)d_in[6],
        (const float*)d_in[7],  (const float*)d_in[8],
        (const float*)d_in[9],  (const float*)d_in[10],
        (float*)d_out);
}

// round 16
// speedup vs baseline: 1.4592x; 1.1214x over previous
#include <cuda_runtime.h>
#include <cstdint>

#define KTOT   4194304
#define CHUNK  64                      // outputs per chain
#define WARM   128                     // warmup window (tile alignment)
#define TS     32                      // steps per tile
#define NT     6                       // tiles per chain
#define WTILES 4                       // warmup tiles (tile 0 half-skipped: eff 112)
#define NCH    (KTOT / CHUNK)          // 65536 chains (1 per thread)
#define WPB    2                       // warps per block
#define TPB    (WPB * 32)
#define NBLK   (NCH / 32 / WPB)        // 1024 blocks (2048 warps)
#define PITCH  34                      // buffer row pitch in floats
#define BROWS  34                      // rows per parity buffer (32 + 2 shift)
#define SGP    18                      // sigma half-buffer pitch

__device__ __forceinline__ float frcp_ap(float x) {
    float r; asm("rcp.approx.ftz.f32 %0, %1;" : "=f"(r) : "f"(x)); return r;
}
__device__ __forceinline__ float fsqrt_ap(float x) {
    float r; asm("sqrt.approx.f32 %0, %1;" : "=f"(r) : "f"(x)); return r;
}
__device__ __forceinline__ void cp_async8(uint32_t dst, const float* src) {
    asm volatile("cp.async.ca.shared.global [%0], [%1], 8;" :: "r"(dst), "l"(src));
}
#define CP_COMMIT() asm volatile("cp.async.commit_group;" ::: "memory")
#define CP_WAIT1()  asm volatile("cp.async.wait_group 1;"  ::: "memory")
#define CP_WAIT0()  asm volatile("cp.async.wait_group 0;"  ::: "memory")

struct P { float nu, Amu, As, bmu, Bs, wmu, ws; };

// 28-cycle recurrence: carries (mu, s2, nus2 = nu*s2).
// All recurrence cycles: {r|nus2}(4) -> d(4) -> RCP(16) -> fma(4) = 28 cyc.
// Numerators pre-scaled off-path inside the RCP shadow.
__device__ __forceinline__ void gas_step(
    const float y, float& mu, float& s2, float& nus2, const P& p)
{
    const float r_  = y - mu;
    const float d   = fmaf(r_, r_, nus2);        // critical: no rr detour
    const float q   = frcp_ap(d);
    const float rr  = r_ * r_;                   // off-path (for a2)
    const float a1  = p.Amu * (s2 * r_);         // ready r+8  < r+24
    const float a2  = p.As  * (s2 * rr);         // ready r+12 < r+24
    const float mb  = fmaf(p.bmu, mu, p.wmu);    // off-path
    const float sb  = fmaf(p.Bs,  s2, p.ws);     // off-path
    mu   = fmaf(a1, q, mb);                      // one op after q
    s2   = fmaf(a2, q, sb);                      // one op after q
    nus2 = p.nu * s2;                            // off the q-chain
}

// Stage rows 0..31 of a parity buffer. Row r holds y[base + 64r, +32).
template<bool GUARD>
__device__ __forceinline__ void stage_init(
    const int base, const int lane, const float* __restrict__ y, float* buf)
{
    const int r0  = lane >> 4;
    const int col = (lane & 15) * 2;
    uint32_t dst = (uint32_t)__cvta_generic_to_shared(buf + r0 * PITCH + col);
    const int g0 = base + r0 * 64 + col;
    #pragma unroll
    for (int k = 0; k < 16; ++k) {               // rows 2k+r0 = 0..31
        int g = g0 + k * 128;
        if (GUARD) g = max(g, 0);                // warp0 pre-t0 slots: skipped
        cp_async8(dst + (uint32_t)(k * (2 * PITCH * 4)), y + g);
    }
    CP_COMMIT();
}

// Stage one extension row (32 floats) of a parity buffer; all lanes commit.
__device__ __forceinline__ void stage_row(
    const int row, const int base, const int lane,
    const float* __restrict__ y, float* buf)
{
    if (lane < 16) {
        uint32_t dst = (uint32_t)__cvta_generic_to_shared(buf + row * PITCH + lane * 2);
        cp_async8(dst, y + base + 64 * row + lane * 2);   // always >= 0 here
    }
    CP_COMMIT();
}

// 16 steps (half tile) from a register preload. EMIT: mu in place, s2 -> sgr.
template<bool GUARD, bool EMIT>
__device__ __forceinline__ void do_half(
    const int t, const int h, const int skip,
    float* rp, float* sgr, float& mu, float& s2, float& nus2, const P& p)
{
    float2 v[8];
    #pragma unroll
    for (int i = 0; i < 8; ++i)                  // 8-deep LDS.64 burst (MLP)
        v[i] = *reinterpret_cast<const float2*>(rp + 16 * h + 2 * i);
    #pragma unroll
    for (int i = 0; i < 8; ++i) {
        if (GUARD) {
            if (t * TS + 16 * h + 2 * i     >= skip) gas_step(v[i].x, mu, s2, nus2, p);
            if (t * TS + 16 * h + 2 * i + 1 >= skip) gas_step(v[i].y, mu, s2, nus2, p);
        } else {
            gas_step(v[i].x, mu, s2, nus2, p);
            const float m0 = mu, v0 = s2;
            gas_step(v[i].y, mu, s2, nus2, p);
            if (EMIT) {
                *reinterpret_cast<float2*>(rp + 16 * h + 2 * i) = make_float2(m0, mu);
                *reinterpret_cast<float2*>(sgr + 2 * i)         = make_float2(v0, s2);
            }
        }
    }
}

// Flush one sigma half: 32 chains x 16 steps, sqrt applied here.
__device__ __forceinline__ void flush_sigma_half(
    const int t, const int h, const int wcb, const int lane,
    const float* sg, float* __restrict__ out)
{
    const int r0 = lane >> 3;
    const int c  = (lane & 7) * 2;
    const int ob = (t - WTILES) * TS + 16 * h;
    #pragma unroll
    for (int k = 0; k < 8; ++k) {
        const int row = 4 * k + r0;
        float2 g = *reinterpret_cast<const float2*>(sg + row * SGP + c);
        g.x = fsqrt_ap(g.x); g.y = fsqrt_ap(g.y);
        *reinterpret_cast<float2*>(&out[KTOT + (wcb + row) * CHUNK + ob + c]) = g;
    }
}

// Flush mu for a whole emit tile: chain i's data sits at buffer row i+ro.
__device__ __forceinline__ void flush_mu(
    const int t, const int ro, const int wcb, const int lane,
    const float* bp, float* __restrict__ out)
{
    const int r0  = lane >> 4;
    const int col = (lane & 15) * 2;
    const int ob  = (t - WTILES) * TS;
    #pragma unroll
    for (int k = 0; k < 16; ++k) {
        const int row = 2 * k + r0;
        const float2 m = *reinterpret_cast<const float2*>(
            bp + (row + ro) * PITCH + col);
        *reinterpret_cast<float2*>(&out[(wcb + row) * CHUNK + ob + col]) = m;
    }
}

template<bool GUARD>
__device__ __forceinline__ void run_warp(
    const int wcb, const int lane,
    const float* __restrict__ y, float* __restrict__ out,
    float* bufE, float* bufO, float* sg,
    float mu, float s2, float nus2, const P& p, const int skip)
{
    const int baseE = wcb * CHUNK - WARM;        // row r of E = y[baseE+64r,+32)
    const int baseO = baseE + 32;                // row r of O = y[baseO+64r,+32)

    stage_init<GUARD>(baseE, lane, y, bufE);     // group 0
    stage_init<GUARD>(baseO, lane, y, bufO);     // group 1

    float* sgr = sg + lane * SGP;

    #pragma unroll 1
    for (int t = 0; t < NT; ++t) {
        if (t < NT - 1) CP_WAIT1(); else CP_WAIT0();
        __syncwarp();
        float* bp = (t & 1) ? bufO : bufE;
        const int ro = t >> 1;
        float* rp = bp + (lane + ro) * PITCH;

        // stage extension row for tile t+2 (same parity): rows 32,32,33,33
        if (t + 2 < NT)
            stage_row(31 + ((t + 2) >> 1), (t & 1) ? baseO : baseE, lane, y, bp);

        if (t < WTILES) {
            if (GUARD) {
                if (t > 0) do_half<true, false>(t, 0, skip, rp, sgr, mu, s2, nus2, p);
                do_half<true,  false>(t, 1, skip, rp, sgr, mu, s2, nus2, p);
            } else {
                // tile 0: skip first half -> effective warmup = 112 steps
                if (t > 0) do_half<false, false>(t, 0, skip, rp, sgr, mu, s2, nus2, p);
                do_half<false, false>(t, 1, skip, rp, sgr, mu, s2, nus2, p);
            }
        } else {
            #pragma unroll
            for (int h = 0; h < 2; ++h) {
                do_half<false, true>(t, h, skip, rp, sgr, mu, s2, nus2, p);
                __syncwarp();
                flush_sigma_half(t, h, wcb, lane, sg, out);
                __syncwarp();                    // sg reads done before reuse
            }
            flush_mu(t, ro, wcb, lane, bp, out);
        }
    }
}

__global__ __launch_bounds__(TPB)
void argas_kernel(
    const float* __restrict__ y,
    const float* __restrict__ p_lastmu,  const float* __restrict__ p_lastsig,
    const float* __restrict__ p_amu,     const float* __restrict__ p_as,
    const float* __restrict__ p_bmu,     const float* __restrict__ p_bs,
    const float* __restrict__ p_wmu,     const float* __restrict__ p_ws,
    const float* __restrict__ p_nu,      const float* __restrict__ p_str,
    float* __restrict__ out)
{
    __shared__ float bufE[WPB][BROWS][PITCH];   // per-warp even-parity rows
    __shared__ float bufO[WPB][BROWS][PITCH];   // per-warp odd-parity rows
    __shared__ float sg[WPB][32][SGP];          // per-warp sigma half-buffer

    const int warp  = threadIdx.x >> 5;
    const int lane  = threadIdx.x & 31;
    const int wcb   = (blockIdx.x * WPB + warp) * 32;   // warp's chain base
    const int chain = wcb + lane;

    P p;
    const float nu       = *p_nu;
    const float strength = *p_str;
    const float amu  = (*p_amu) * strength;
    const float as_  = (*p_as)  * strength;
    const float bmu  = *p_bmu;
    const float bs   = *p_bs;
    const float nup1 = nu + 1.0f;
    p.nu  = nu;
    p.Amu = bmu * amu * nup1;
    p.As  = bs  * as_ * nup1;
    p.bmu = bmu;
    p.Bs  = bs * (1.0f - as_);
    p.wmu = *p_wmu;
    p.ws  = *p_ws;

    const float mu0   = *p_lastmu;  // chains whose warmup reaches before idx 0
    const float s20   = *p_lastsig; // skip those steps; they start exact.
    const float nus20 = nu * s20;

    const int skip = WARM - chain * CHUNK;   // >0 only for chains 0,1 (warp 0)

    if (wcb == 0)
        run_warp<true >(wcb, lane, y, out,
                        &bufE[warp][0][0], &bufO[warp][0][0], &sg[warp][0][0],
                        mu0, s20, nus20, p, skip);
    else
        run_warp<false>(wcb, lane, y, out,
                        &bufE[warp][0][0], &bufO[warp][0][0], &sg[warp][0][0],
                        mu0, s20, nus20, p, skip);
}

extern "C" void kernel_launch(void* const* d_in, const int* in_sizes, int n_in,
                              void* d_out, int out_size) {
    const float* y = (const float*)d_in[0];
    argas_kernel<<<NBLK, TPB>>>(
        y,
        (const float*)d_in[1],  (const float*)d_in[2],
        (const float*)d_in[3],  (const float*)d_in[4],
        (const float*)d_in[5],  (const float*)d_in[6],
        (const float*)d_in[7],  (const float*)d_in[8],
        (const float*)d_in[9],  (const float*)d_in[10],
        (float*)d_out);
}